// round 3
// baseline (speedup 1.0000x reference)
#include <cuda_runtime.h>
#include <math.h>

// Problem constants (fixed by the dataset)
#define N_NODES 30000
#define E_EDGES 480000
#define E_TOT   (E_EDGES + N_NODES)   // edges + self loops = 510000
#define G_GRAPHS 128
#define MAXF 192                      // max H*C across layers

// ---------------- scratch (static device globals; no allocation) -------------
__device__ float g_x  [N_NODES * MAXF];  // node features between layers
__device__ float g_xl [N_NODES * MAXF];
__device__ float g_xr [N_NODES * MAXF];
__device__ float g_acc[N_NODES * MAXF];  // aggregation accumulator
__device__ float g_p  [E_TOT * 3];       // per (edge, head) logit -> prob
__device__ float g_m  [N_NODES * 3];     // segment max
__device__ float g_den[N_NODES * 3];     // segment sum
__device__ float g_gs [G_GRAPHS * 64];   // graph pooled sums
__device__ float g_cnt[G_GRAPHS];        // graph node counts

// ---------------- helpers ----------------------------------------------------
__device__ __forceinline__ void atomicMaxFloat(float* addr, float val) {
    int old = __float_as_int(*addr);
    while (__int_as_float(old) < val) {
        int assumed = old;
        old = atomicCAS((int*)addr, assumed, __float_as_int(val));
        if (old == assumed) break;
    }
}

__device__ __forceinline__ void edge_endpoints(int e, const int* __restrict__ ei,
                                               int& src, int& dst) {
    if (e < E_EDGES) { src = ei[e]; dst = ei[E_EDGES + e]; }
    else             { src = dst = e - E_EDGES; }
}

// ---------------- kernels -----------------------------------------------------
__global__ void k_fill(float* __restrict__ p, float v, int n) {
    int i = blockIdx.x * blockDim.x + threadIdx.x;
    if (i < n) p[i] = v;
}

__global__ void k_gather(const float* __restrict__ emb, const int* __restrict__ ids,
                         float* __restrict__ x) {
    int i = blockIdx.x * blockDim.x + threadIdx.x;
    if (i >= N_NODES * 16) return;
    int n = i >> 4, c = i & 15;
    x[i] = emb[ids[n] * 16 + c];
}

// Y[row, col] = X[row,:] @ W[:,col] + b[col].  One block per row, blockDim.x == M.
__global__ void k_gemm_bias(const float* __restrict__ X, const float* __restrict__ W,
                            const float* __restrict__ b, float* __restrict__ Y,
                            int K, int M) {
    extern __shared__ float sx[];
    int row = blockIdx.x;
    for (int k = threadIdx.x; k < K; k += blockDim.x) sx[k] = X[row * K + k];
    __syncthreads();
    int col = threadIdx.x;
    if (col < M) {
        float acc = b[col];
        #pragma unroll 8
        for (int k = 0; k < K; k++) acc = fmaf(sx[k], W[k * M + col], acc);
        Y[row * M + col] = acc;
    }
}

// One warp per (edge, head): logit = att[h,:] . leaky_relu(xl[src,h,:] + xr[dst,h,:])
__global__ void k_edge_logit(const float* __restrict__ xl, const float* __restrict__ xr,
                             const float* __restrict__ att, const int* __restrict__ ei,
                             float* __restrict__ logit, float* __restrict__ m,
                             int H, int C) {
    int warp = (blockIdx.x * blockDim.x + threadIdx.x) >> 5;
    int lane = threadIdx.x & 31;
    if (warp >= E_TOT * H) return;
    int e = warp / H, h = warp - e * H;
    int src, dst; edge_endpoints(e, ei, src, dst);
    int HC = H * C;
    const float* a  = att + h * C;
    const float* pl = xl + (size_t)src * HC + h * C;
    const float* pr = xr + (size_t)dst * HC + h * C;
    float s = 0.f;
    for (int c = lane; c < C; c += 32) {
        float v = pl[c] + pr[c];
        v = (v > 0.f) ? v : 0.2f * v;
        s = fmaf(a[c], v, s);
    }
    #pragma unroll
    for (int o = 16; o; o >>= 1) s += __shfl_down_sync(0xffffffffu, s, o);
    if (lane == 0) {
        logit[warp] = s;
        atomicMaxFloat(&m[dst * H + h], s);
    }
}

// p = exp(logit - m[dst]); denom[dst] += p
__global__ void k_edge_exp(float* __restrict__ logit, const float* __restrict__ m,
                           float* __restrict__ den, const int* __restrict__ ei, int H) {
    int idx = blockIdx.x * blockDim.x + threadIdx.x;
    if (idx >= E_TOT * H) return;
    int e = idx / H, h = idx - e * H;
    int src, dst; edge_endpoints(e, ei, src, dst);
    float p = expf(logit[idx] - m[dst * H + h]);
    logit[idx] = p;
    atomicAdd(&den[dst * H + h], p);
}

// acc[dst, j] += xl[src, j] * p/denom  — one thread per (edge, j), j in [0, H*C)
__global__ void k_aggregate(const float* __restrict__ p, const float* __restrict__ den,
                            const float* __restrict__ xl, const int* __restrict__ ei,
                            float* __restrict__ acc, int H, int C, int HC) {
    int idx = blockIdx.x * blockDim.x + threadIdx.x;
    int tot = E_TOT * HC;
    if (idx >= tot) return;
    int e = idx / HC, j = idx - e * HC;
    int h = j / C;
    int src, dst; edge_endpoints(e, ei, src, dst);
    float alpha = p[e * H + h] / den[dst * H + h];
    atomicAdd(&acc[(size_t)dst * HC + j], xl[(size_t)src * HC + j] * alpha);
}

__global__ void k_finalize(const float* __restrict__ acc, const float* __restrict__ bo,
                           float* __restrict__ x, int M) {
    int idx = blockIdx.x * blockDim.x + threadIdx.x;
    if (idx >= N_NODES * M) return;
    x[idx] = acc[idx] + bo[idx % M];
}

__global__ void k_pool(const float* __restrict__ x, const int* __restrict__ batch,
                       float* __restrict__ gs, float* __restrict__ cnt) {
    int idx = blockIdx.x * blockDim.x + threadIdx.x;
    if (idx >= N_NODES * 64) return;
    int i = idx >> 6, j = idx & 63;
    int b = batch[i];
    atomicAdd(&gs[b * 64 + j], x[i * 64 + j]);
    if (j == 0) atomicAdd(&cnt[b], 1.0f);
}

__global__ void k_mlp(const float* __restrict__ gs, const float* __restrict__ cnt,
                      const float* __restrict__ demo,
                      const float* __restrict__ Wc1, const float* __restrict__ bc1,
                      const float* __restrict__ Wc2, const float* __restrict__ bc2,
                      float* __restrict__ out) {
    int g = blockIdx.x * blockDim.x + threadIdx.x;
    if (g >= G_GRAPHS) return;
    float inv = 1.0f / fmaxf(cnt[g], 1.0f);
    float in[69];
    #pragma unroll
    for (int j = 0; j < 64; j++) in[j] = gs[g * 64 + j] * inv;
    #pragma unroll
    for (int j = 0; j < 5; j++) in[64 + j] = demo[g * 5 + j];
    float h[32];
    #pragma unroll
    for (int o = 0; o < 32; o++) {
        float a = bc1[o];
        for (int i = 0; i < 69; i++) a = fmaf(in[i], Wc1[i * 32 + o], a);
        h[o] = fmaxf(a, 0.0f);
    }
    #pragma unroll
    for (int o = 0; o < 2; o++) {
        float a = bc2[o];
        #pragma unroll
        for (int i = 0; i < 32; i++) a = fmaf(h[i], Wc2[i * 2 + o], a);
        out[g * 2 + o] = a;
    }
}

// ---------------- launch ------------------------------------------------------
static inline int ceil_div(int a, int b) { return (a + b - 1) / b; }

extern "C" void kernel_launch(void* const* d_in, const int* in_sizes, int n_in,
                              void* d_out, int out_size) {
    const float* emb  = (const float*)d_in[0];
    const float* Wl0  = (const float*)d_in[1];
    const float* bl0  = (const float*)d_in[2];
    const float* Wr0  = (const float*)d_in[3];
    const float* br0  = (const float*)d_in[4];
    const float* att0 = (const float*)d_in[5];
    const float* bo0  = (const float*)d_in[6];
    const float* Wl1  = (const float*)d_in[7];
    const float* bl1  = (const float*)d_in[8];
    const float* Wr1  = (const float*)d_in[9];
    const float* br1  = (const float*)d_in[10];
    const float* att1 = (const float*)d_in[11];
    const float* bo1  = (const float*)d_in[12];
    const float* Wl2  = (const float*)d_in[13];
    const float* bl2  = (const float*)d_in[14];
    const float* Wr2  = (const float*)d_in[15];
    const float* br2  = (const float*)d_in[16];
    const float* att2 = (const float*)d_in[17];
    const float* bo2  = (const float*)d_in[18];
    const float* Wc1  = (const float*)d_in[19];
    const float* bc1  = (const float*)d_in[20];
    const float* Wc2  = (const float*)d_in[21];
    const float* bc2  = (const float*)d_in[22];
    const float* demo = (const float*)d_in[23];
    const int*   ids  = (const int*)d_in[24];
    const int*   ei   = (const int*)d_in[25];
    const int*   batch= (const int*)d_in[26];
    float* out = (float*)d_out;

    float *px, *pxl, *pxr, *pacc, *pp, *pm, *pden, *pgs, *pcnt;
    cudaGetSymbolAddress((void**)&px,   g_x);
    cudaGetSymbolAddress((void**)&pxl,  g_xl);
    cudaGetSymbolAddress((void**)&pxr,  g_xr);
    cudaGetSymbolAddress((void**)&pacc, g_acc);
    cudaGetSymbolAddress((void**)&pp,   g_p);
    cudaGetSymbolAddress((void**)&pm,   g_m);
    cudaGetSymbolAddress((void**)&pden, g_den);
    cudaGetSymbolAddress((void**)&pgs,  g_gs);
    cudaGetSymbolAddress((void**)&pcnt, g_cnt);

    const int TB = 256;

    // node embedding gather -> g_x [N,16]
    k_gather<<<ceil_div(N_NODES * 16, TB), TB>>>(emb, ids, px);

    // one GATv2 layer: input px [N,K] -> output px [N,H*C]
    auto layer = [&](const float* Wl, const float* bl, const float* Wr, const float* br,
                     const float* att, const float* bo, int K, int H, int C) {
        int M = H * C;
        k_gemm_bias<<<N_NODES, M, K * (int)sizeof(float)>>>(px, Wl, bl, pxl, K, M);
        k_gemm_bias<<<N_NODES, M, K * (int)sizeof(float)>>>(px, Wr, br, pxr, K, M);
        k_fill<<<ceil_div(N_NODES * H, TB), TB>>>(pm, -INFINITY, N_NODES * H);
        k_fill<<<ceil_div(N_NODES * H, TB), TB>>>(pden, 0.0f, N_NODES * H);
        int nwh = E_TOT * H;
        k_edge_logit<<<ceil_div(nwh * 32, TB), TB>>>(pxl, pxr, att, ei, pp, pm, H, C);
        k_edge_exp<<<ceil_div(nwh, TB), TB>>>(pp, pm, pden, ei, H);
        k_fill<<<ceil_div(N_NODES * M, TB), TB>>>(pacc, 0.0f, N_NODES * M);
        k_aggregate<<<ceil_div(E_TOT * M, TB), TB>>>(pp, pden, pxl, ei, pacc, H, C, M);
        k_finalize<<<ceil_div(N_NODES * M, TB), TB>>>(pacc, bo, px, M);
    };

    layer(Wl0, bl0, Wr0, br0, att0, bo0, 16, 3, 32);
    layer(Wl1, bl1, Wr1, br1, att1, bo1, 96, 2, 96);
    layer(Wl2, bl2, Wr2, br2, att2, bo2, 192, 1, 64);

    // global mean pool + MLP head  (grids sized to cover the full arrays!)
    k_fill<<<ceil_div(G_GRAPHS * 64, TB), TB>>>(pgs, 0.0f, G_GRAPHS * 64);
    k_fill<<<1, G_GRAPHS>>>(pcnt, 0.0f, G_GRAPHS);
    k_pool<<<ceil_div(N_NODES * 64, TB), TB>>>(px, batch, pgs, pcnt);
    k_mlp<<<1, G_GRAPHS>>>(pgs, pcnt, demo, Wc1, bc1, Wc2, bc2, out);
}

// round 4
// speedup vs baseline: 2.1976x; 2.1976x over previous
#include <cuda_runtime.h>
#include <math.h>

// Problem constants (fixed by the dataset)
#define N_NODES 30000
#define E_EDGES 480000
#define E_TOT   (E_EDGES + N_NODES)   // edges + self loops = 510000
#define G_GRAPHS 128
#define MAXF 192
#define TB 128                        // threads per block in attention kernel

// ---------------- scratch (static device globals; no allocation) -------------
__device__ float g_x  [N_NODES * MAXF];   // node features between layers
__device__ float g_xl [N_NODES * MAXF];
__device__ float g_xr [N_NODES * MAXF];
__device__ float g_p  [E_TOT * 3];        // per (csr-pos, head) logit -> prob
__device__ int   g_deg[N_NODES];          // in-degree counts
__device__ int   g_rp [N_NODES + 1];      // CSR row pointers (by dst)
__device__ int   g_cur[N_NODES];          // fill cursors
__device__ int   g_csrc[E_TOT];           // CSR: src node per position
__device__ float g_gs [G_GRAPHS * 64];    // pooled sums
__device__ float g_cnt[G_GRAPHS];         // node counts per graph

// ---------------- small utility kernels --------------------------------------
__global__ void k_fill_f(float* __restrict__ p, float v, int n) {
    int i = blockIdx.x * blockDim.x + threadIdx.x;
    if (i < n) p[i] = v;
}
__global__ void k_fill_i(int* __restrict__ p, int v, int n) {
    int i = blockIdx.x * blockDim.x + threadIdx.x;
    if (i < n) p[i] = v;
}

__global__ void k_gather(const float* __restrict__ emb, const int* __restrict__ ids,
                         float* __restrict__ x) {
    int i = blockIdx.x * blockDim.x + threadIdx.x;
    if (i >= N_NODES * 16) return;
    int n = i >> 4, c = i & 15;
    x[i] = emb[ids[n] * 16 + c];
}

// ---------------- CSR build (by destination) ----------------------------------
__global__ void k_count(const int* __restrict__ ei, int* __restrict__ deg) {
    int e = blockIdx.x * blockDim.x + threadIdx.x;
    if (e >= E_TOT) return;
    int dst = (e < E_EDGES) ? ei[E_EDGES + e] : (e - E_EDGES);
    atomicAdd(&deg[dst], 1);
}

__global__ void k_scan(const int* __restrict__ deg, int* __restrict__ rp,
                       int* __restrict__ cur) {
    const int T = 1024;
    __shared__ int part[T];
    int tid = threadIdx.x;
    const int per = (N_NODES + T - 1) / T;
    int lo = tid * per, hi = min(lo + per, N_NODES);
    int s = 0;
    for (int i = lo; i < hi; i++) s += deg[i];
    part[tid] = s;
    __syncthreads();
    for (int off = 1; off < T; off <<= 1) {
        int v = (tid >= off) ? part[tid - off] : 0;
        __syncthreads();
        part[tid] += v;
        __syncthreads();
    }
    int run = (tid > 0) ? part[tid - 1] : 0;
    for (int i = lo; i < hi; i++) { rp[i] = run; cur[i] = run; run += deg[i]; }
    if (tid == T - 1) rp[N_NODES] = run;
}

__global__ void k_scatter(const int* __restrict__ ei, int* __restrict__ cur,
                          int* __restrict__ csrc) {
    int e = blockIdx.x * blockDim.x + threadIdx.x;
    if (e >= E_TOT) return;
    int src, dst;
    if (e < E_EDGES) { src = ei[e]; dst = ei[E_EDGES + e]; }
    else             { src = dst = e - E_EDGES; }
    int pos = atomicAdd(&cur[dst], 1);
    csrc[pos] = src;
}

// ---------------- row-tiled dual GEMM (xl and xr in one pass) ------------------
// block = M threads, handles ROWS rows; X tile cached in smem; each thread owns
// one output column and ROWS accumulators for each of the two weight matrices.
template <int K, int M, int ROWS>
__global__ void k_gemm2(const float* __restrict__ X,
                        const float* __restrict__ Wl, const float* __restrict__ bl,
                        const float* __restrict__ Wr, const float* __restrict__ br,
                        float* __restrict__ Yl, float* __restrict__ Yr) {
    __shared__ float sx[ROWS * K];
    int row0 = blockIdx.x * ROWS;
    int nr = min(ROWS, N_NODES - row0);
    for (int i = threadIdx.x; i < nr * K; i += M) sx[i] = X[(size_t)row0 * K + i];
    __syncthreads();
    int c = threadIdx.x;  // 0..M-1
    float al[ROWS], ar[ROWS];
    float blc = bl[c], brc = br[c];
    #pragma unroll
    for (int r = 0; r < ROWS; r++) { al[r] = blc; ar[r] = brc; }
    for (int k = 0; k < K; k++) {
        float wl = Wl[k * M + c], wr = Wr[k * M + c];
        #pragma unroll
        for (int r = 0; r < ROWS; r++) {
            float xv = sx[r * K + k];
            al[r] = fmaf(xv, wl, al[r]);
            ar[r] = fmaf(xv, wr, ar[r]);
        }
    }
    for (int r = 0; r < nr; r++) {
        Yl[(size_t)(row0 + r) * M + c] = al[r];
        Yr[(size_t)(row0 + r) * M + c] = ar[r];
    }
}

// ---------------- fused attention + aggregation (block per dst node) -----------
// logits -> segment max -> exp/denominator -> alpha-weighted gather + bias,
// all reductions in shared memory (no global atomics).
template <int H, int C>
__global__ void k_attn(const float* __restrict__ xl, const float* __restrict__ xr,
                       const float* __restrict__ att, const float* __restrict__ bo,
                       const int* __restrict__ rp, const int* __restrict__ csrc,
                       float* __restrict__ p, float* __restrict__ out) {
    constexpr int M  = H * C;
    constexpr int CH = 128;                 // aggregate chunk
    constexpr int Q  = (M + TB - 1) / TB;   // outputs per thread
    __shared__ float s_xr[M], s_att[M];
    __shared__ float s_m[H], s_den[H];
    __shared__ int   s_src[CH];
    __shared__ float s_alpha[CH * H];

    int dst = blockIdx.x;
    int tid = threadIdx.x;
    int start = rp[dst];
    int deg   = rp[dst + 1] - start;

    for (int j = tid; j < M; j += TB) { s_xr[j] = xr[(size_t)dst * M + j]; s_att[j] = att[j]; }
    if (tid < H) { s_m[tid] = -INFINITY; s_den[tid] = 0.f; }
    __syncthreads();

    // phase 1: logits (warp per edge), block max per head via shared CAS
    int wid = tid >> 5, lane = tid & 31;
    for (int e = wid; e < deg; e += TB / 32) {
        int pos = start + e;
        const float* xls = xl + (size_t)csrc[pos] * M;
        #pragma unroll
        for (int h = 0; h < H; h++) {
            float s = 0.f;
            #pragma unroll
            for (int c = lane; c < C; c += 32) {
                int j = h * C + c;
                float v = xls[j] + s_xr[j];
                v = (v > 0.f) ? v : 0.2f * v;
                s = fmaf(s_att[j], v, s);
            }
            #pragma unroll
            for (int o = 16; o; o >>= 1) s += __shfl_xor_sync(0xffffffffu, s, o);
            if (lane == 0) {
                p[(size_t)pos * H + h] = s;
                int* a = (int*)&s_m[h];
                int old = *a;
                while (__int_as_float(old) < s) {
                    int assumed = old;
                    old = atomicCAS(a, assumed, __float_as_int(s));
                    if (old == assumed) break;
                }
            }
        }
    }
    __syncthreads();

    // phase 2: exp + denominator (positions contiguous -> linear index)
    for (int i = tid; i < deg * H; i += TB) {
        int h = i % H;
        float v = expf(p[(size_t)start * H + i] - s_m[h]);
        p[(size_t)start * H + i] = v;
        atomicAdd(&s_den[h], v);
    }
    __syncthreads();

    // phase 3: weighted gather-aggregate, chunked through smem
    float acc[Q];
    #pragma unroll
    for (int q = 0; q < Q; q++) acc[q] = 0.f;
    for (int base = 0; base < deg; base += CH) {
        int n = min(CH, deg - base);
        __syncthreads();
        for (int i = tid; i < n; i += TB) s_src[i] = csrc[start + base + i];
        for (int i = tid; i < n * H; i += TB)
            s_alpha[i] = p[(size_t)(start + base) * H + i] / s_den[i % H];
        __syncthreads();
        for (int e = 0; e < n; e++) {
            const float* xls = xl + (size_t)s_src[e] * M;
            #pragma unroll
            for (int q = 0; q < Q; q++) {
                int j = tid + q * TB;
                if (j < M) acc[q] = fmaf(s_alpha[e * H + j / C], xls[j], acc[q]);
            }
        }
    }
    #pragma unroll
    for (int q = 0; q < Q; q++) {
        int j = tid + q * TB;
        if (j < M) out[(size_t)dst * M + j] = acc[q] + bo[j];
    }
}

// ---------------- pooling (exploits sorted batch: run-length local sums) -------
__global__ void k_pool2(const float* __restrict__ x, const int* __restrict__ batch,
                        float* __restrict__ gs, float* __restrict__ cnt) {
    int j = threadIdx.x;              // 0..63 feature
    int w = threadIdx.y;              // 0..3
    int i0 = blockIdx.x * 128;
    int iend = min(i0 + 128, N_NODES);
    float acc = 0.f, cn = 0.f;
    int curb = -1;
    for (int i = i0 + w; i < iend; i += 4) {
        int b = batch[i];
        if (b != curb) {
            if (curb >= 0) {
                atomicAdd(&gs[curb * 64 + j], acc);
                if (j == 0) atomicAdd(&cnt[curb], cn);
            }
            curb = b; acc = 0.f; cn = 0.f;
        }
        acc += x[(size_t)i * 64 + j];
        cn += 1.f;
    }
    if (curb >= 0) {
        atomicAdd(&gs[curb * 64 + j], acc);
        if (j == 0) atomicAdd(&cnt[curb], cn);
    }
}

__global__ void k_mlp(const float* __restrict__ gs, const float* __restrict__ cnt,
                      const float* __restrict__ demo,
                      const float* __restrict__ Wc1, const float* __restrict__ bc1,
                      const float* __restrict__ Wc2, const float* __restrict__ bc2,
                      float* __restrict__ out) {
    int g = blockIdx.x * blockDim.x + threadIdx.x;
    if (g >= G_GRAPHS) return;
    float inv = 1.0f / fmaxf(cnt[g], 1.0f);
    float in[69];
    #pragma unroll
    for (int j = 0; j < 64; j++) in[j] = gs[g * 64 + j] * inv;
    #pragma unroll
    for (int j = 0; j < 5; j++) in[64 + j] = demo[g * 5 + j];
    float h[32];
    #pragma unroll
    for (int o = 0; o < 32; o++) {
        float a = bc1[o];
        for (int i = 0; i < 69; i++) a = fmaf(in[i], Wc1[i * 32 + o], a);
        h[o] = fmaxf(a, 0.0f);
    }
    #pragma unroll
    for (int o = 0; o < 2; o++) {
        float a = bc2[o];
        #pragma unroll
        for (int i = 0; i < 32; i++) a = fmaf(h[i], Wc2[i * 2 + o], a);
        out[g * 2 + o] = a;
    }
}

// ---------------- launch ------------------------------------------------------
static inline int ceil_div(int a, int b) { return (a + b - 1) / b; }

extern "C" void kernel_launch(void* const* d_in, const int* in_sizes, int n_in,
                              void* d_out, int out_size) {
    const float* emb  = (const float*)d_in[0];
    const float* Wl0  = (const float*)d_in[1];
    const float* bl0  = (const float*)d_in[2];
    const float* Wr0  = (const float*)d_in[3];
    const float* br0  = (const float*)d_in[4];
    const float* att0 = (const float*)d_in[5];
    const float* bo0  = (const float*)d_in[6];
    const float* Wl1  = (const float*)d_in[7];
    const float* bl1  = (const float*)d_in[8];
    const float* Wr1  = (const float*)d_in[9];
    const float* br1  = (const float*)d_in[10];
    const float* att1 = (const float*)d_in[11];
    const float* bo1  = (const float*)d_in[12];
    const float* Wl2  = (const float*)d_in[13];
    const float* bl2  = (const float*)d_in[14];
    const float* Wr2  = (const float*)d_in[15];
    const float* br2  = (const float*)d_in[16];
    const float* att2 = (const float*)d_in[17];
    const float* bo2  = (const float*)d_in[18];
    const float* Wc1  = (const float*)d_in[19];
    const float* bc1  = (const float*)d_in[20];
    const float* Wc2  = (const float*)d_in[21];
    const float* bc2  = (const float*)d_in[22];
    const float* demo = (const float*)d_in[23];
    const int*   ids  = (const int*)d_in[24];
    const int*   ei   = (const int*)d_in[25];
    const int*   batch= (const int*)d_in[26];
    float* out = (float*)d_out;

    float *px, *pxl, *pxr, *pp, *pgs, *pcnt;
    int *pdeg, *prp, *pcur, *pcsrc;
    cudaGetSymbolAddress((void**)&px,    g_x);
    cudaGetSymbolAddress((void**)&pxl,   g_xl);
    cudaGetSymbolAddress((void**)&pxr,   g_xr);
    cudaGetSymbolAddress((void**)&pp,    g_p);
    cudaGetSymbolAddress((void**)&pdeg,  g_deg);
    cudaGetSymbolAddress((void**)&prp,   g_rp);
    cudaGetSymbolAddress((void**)&pcur,  g_cur);
    cudaGetSymbolAddress((void**)&pcsrc, g_csrc);
    cudaGetSymbolAddress((void**)&pgs,   g_gs);
    cudaGetSymbolAddress((void**)&pcnt,  g_cnt);

    const int T = 256;

    // embedding gather
    k_gather<<<ceil_div(N_NODES * 16, T), T>>>(emb, ids, px);

    // CSR by destination (shared by all three layers)
    k_fill_i<<<ceil_div(N_NODES, T), T>>>(pdeg, 0, N_NODES);
    k_count<<<ceil_div(E_TOT, T), T>>>(ei, pdeg);
    k_scan<<<1, 1024>>>(pdeg, prp, pcur);
    k_scatter<<<ceil_div(E_TOT, T), T>>>(ei, pcur, pcsrc);

    // layer 0: 16 -> 3 heads x 32
    k_gemm2<16, 96, 32><<<ceil_div(N_NODES, 32), 96>>>(px, Wl0, bl0, Wr0, br0, pxl, pxr);
    k_attn<3, 32><<<N_NODES, TB>>>(pxl, pxr, att0, bo0, prp, pcsrc, pp, px);

    // layer 1: 96 -> 2 heads x 96
    k_gemm2<96, 192, 32><<<ceil_div(N_NODES, 32), 192>>>(px, Wl1, bl1, Wr1, br1, pxl, pxr);
    k_attn<2, 96><<<N_NODES, TB>>>(pxl, pxr, att1, bo1, prp, pcsrc, pp, px);

    // layer 2: 192 -> 1 head x 64
    k_gemm2<192, 64, 32><<<ceil_div(N_NODES, 32), 64>>>(px, Wl2, bl2, Wr2, br2, pxl, pxr);
    k_attn<1, 64><<<N_NODES, TB>>>(pxl, pxr, att2, bo2, prp, pcsrc, pp, px);

    // global mean pool + MLP head
    k_fill_f<<<ceil_div(G_GRAPHS * 64, T), T>>>(pgs, 0.0f, G_GRAPHS * 64);
    k_fill_f<<<1, G_GRAPHS>>>(pcnt, 0.0f, G_GRAPHS);
    dim3 pb(64, 4);
    k_pool2<<<ceil_div(N_NODES, 128), pb>>>(px, batch, pgs, pcnt);
    k_mlp<<<1, G_GRAPHS>>>(pgs, pcnt, demo, Wc1, bc1, Wc2, bc2, out);
}

// round 7
// speedup vs baseline: 2.8951x; 1.3174x over previous
#include <cuda_runtime.h>
#include <math.h>

// Problem constants (fixed by the dataset)
#define N_NODES 30000
#define E_EDGES 480000
#define E_TOT   (E_EDGES + N_NODES)   // edges + self loops = 510000
#define G_GRAPHS 128
#define MAXF 192
#define TB 128                        // threads per block in attention kernel
#define SCAN_B 1024
#define SCAN_NB ((N_NODES + SCAN_B - 1) / SCAN_B)

typedef unsigned long long ull;

// ---------------- scratch (static device globals; no allocation) -------------
__device__ float g_x   [N_NODES * MAXF];
__device__ float g_xl  [N_NODES * MAXF];
__device__ float g_xr  [N_NODES * MAXF];
__device__ float g_p   [E_TOT * 3];       // fallback prob buffer (deg > CAP)
__device__ int   g_deg [N_NODES];
__device__ int   g_rp  [N_NODES + 1];
__device__ int   g_cur [N_NODES];
__device__ int   g_csrc[E_TOT];
__device__ int   g_part[SCAN_NB];
__device__ float g_gs  [G_GRAPHS * 64];
__device__ float g_cnt [G_GRAPHS];

// ---------------- f32x2 helpers ------------------------------------------------
__device__ __forceinline__ ull pack2(float lo, float hi) {
    ull r; asm("mov.b64 %0, {%1, %2};" : "=l"(r) : "f"(lo), "f"(hi)); return r;
}
__device__ __forceinline__ void fma2(ull& acc, ull a, ull b) {
    asm("fma.rn.f32x2 %0, %1, %2, %3;" : "=l"(acc) : "l"(a), "l"(b), "l"(acc));
}

// ---------------- small utility kernels ----------------------------------------
__global__ void k_fill_f(float* __restrict__ p, float v, int n) {
    int i = blockIdx.x * blockDim.x + threadIdx.x;
    if (i < n) p[i] = v;
}
__global__ void k_fill_i(int* __restrict__ p, int v, int n) {
    int i = blockIdx.x * blockDim.x + threadIdx.x;
    if (i < n) p[i] = v;
}

__global__ void k_gather(const float* __restrict__ emb, const int* __restrict__ ids,
                         float* __restrict__ x) {
    int i = blockIdx.x * blockDim.x + threadIdx.x;
    if (i >= N_NODES * 16) return;
    int n = i >> 4, c = i & 15;
    x[i] = emb[ids[n] * 16 + c];
}

// ---------------- CSR build (by destination) -----------------------------------
__global__ void k_count(const int* __restrict__ ei, int* __restrict__ deg) {
    int e = blockIdx.x * blockDim.x + threadIdx.x;
    if (e >= E_TOT) return;
    int dst = (e < E_EDGES) ? ei[E_EDGES + e] : (e - E_EDGES);
    atomicAdd(&deg[dst], 1);
}

// parallel scan, 3 stages
__global__ void k_scan1(const int* __restrict__ deg, int* __restrict__ part) {
    __shared__ int sm[SCAN_B];
    int i = blockIdx.x * SCAN_B + threadIdx.x;
    sm[threadIdx.x] = (i < N_NODES) ? deg[i] : 0;
    __syncthreads();
    for (int o = SCAN_B / 2; o; o >>= 1) {
        if (threadIdx.x < o) sm[threadIdx.x] += sm[threadIdx.x + o];
        __syncthreads();
    }
    if (threadIdx.x == 0) part[blockIdx.x] = sm[0];
}
__global__ void k_scan2(int* __restrict__ part) {
    int run = 0;
    for (int b = 0; b < SCAN_NB; b++) { int v = part[b]; part[b] = run; run += v; }
}
__global__ void k_scan3(const int* __restrict__ deg, const int* __restrict__ part,
                        int* __restrict__ rp, int* __restrict__ cur) {
    __shared__ int sm[SCAN_B];
    int i = blockIdx.x * SCAN_B + threadIdx.x;
    int v = (i < N_NODES) ? deg[i] : 0;
    sm[threadIdx.x] = v;
    __syncthreads();
    for (int o = 1; o < SCAN_B; o <<= 1) {
        int t = (threadIdx.x >= o) ? sm[threadIdx.x - o] : 0;
        __syncthreads();
        sm[threadIdx.x] += t;
        __syncthreads();
    }
    int excl = sm[threadIdx.x] - v + part[blockIdx.x];
    if (i < N_NODES) { rp[i] = excl; cur[i] = excl; }
    if (i == N_NODES - 1) rp[N_NODES] = excl + v;
}

__global__ void k_scatter(const int* __restrict__ ei, int* __restrict__ cur,
                          int* __restrict__ csrc) {
    int e = blockIdx.x * blockDim.x + threadIdx.x;
    if (e >= E_TOT) return;
    int src, dst;
    if (e < E_EDGES) { src = ei[e]; dst = ei[E_EDGES + e]; }
    else             { src = dst = e - E_EDGES; }
    int pos = atomicAdd(&cur[dst], 1);
    csrc[pos] = src;
}

// ---------------- row-tiled dual GEMM with packed f32x2 FMA ---------------------
// block = M threads, ROWS=32 rows per block, X tile transposed in smem.
template <int K, int M, int ROWS>
__global__ void k_gemm2(const float* __restrict__ X,
                        const float* __restrict__ Wl, const float* __restrict__ bl,
                        const float* __restrict__ Wr, const float* __restrict__ br,
                        float* __restrict__ Yl, float* __restrict__ Yr) {
    constexpr int PAD = ROWS + 2;      // even pad: 8B alignment + few bank conflicts
    constexpr int NP  = ROWS / 2;      // row pairs
    __shared__ __align__(16) float sxt[K * PAD];
    int row0 = blockIdx.x * ROWS;
    int nr = min(ROWS, N_NODES - row0);
    for (int i = threadIdx.x; i < nr * K; i += M) {
        int r = i / K, k = i - r * K;
        sxt[k * PAD + r] = X[(size_t)row0 * K + i];
    }
    // zero unused rows so packed lanes stay finite (cheap, avoids stale smem)
    for (int i = threadIdx.x; i < (ROWS - nr) * K; i += M) {
        int r = nr + i / K, k = i - (i / K) * K;
        sxt[k * PAD + r] = 0.0f;
    }
    __syncthreads();

    int c = threadIdx.x;  // 0..M-1
    ull al[NP], ar[NP];
    {
        ull bl2 = pack2(bl[c], bl[c]);
        ull br2 = pack2(br[c], br[c]);
        #pragma unroll
        for (int p = 0; p < NP; p++) { al[p] = bl2; ar[p] = br2; }
    }
    #pragma unroll 4
    for (int k = 0; k < K; k++) {
        float wl = Wl[k * M + c], wr = Wr[k * M + c];
        ull wl2 = pack2(wl, wl), wr2 = pack2(wr, wr);
        const float* rowp = &sxt[k * PAD];
        #pragma unroll
        for (int p = 0; p < NP; p++) {
            ull xv = *(const ull*)(rowp + 2 * p);   // two rows, broadcast LDS.64
            fma2(al[p], xv, wl2);
            fma2(ar[p], xv, wr2);
        }
    }
    #pragma unroll
    for (int p = 0; p < NP; p++) {
        float2 ul = *(float2*)&al[p];
        float2 ur = *(float2*)&ar[p];
        int r0 = 2 * p;
        if (r0 < nr) {
            Yl[(size_t)(row0 + r0) * M + c] = ul.x;
            Yr[(size_t)(row0 + r0) * M + c] = ur.x;
        }
        if (r0 + 1 < nr) {
            Yl[(size_t)(row0 + r0 + 1) * M + c] = ul.y;
            Yr[(size_t)(row0 + r0 + 1) * M + c] = ur.y;
        }
    }
}

// ---------------- fused attention + aggregation (block per dst node) ------------
// probs and src indices live in smem when deg <= CAP (always true for this data);
// deterministic global fallback otherwise.
template <int H, int C>
__global__ void k_attn(const float* __restrict__ xl, const float* __restrict__ xr,
                       const float* __restrict__ att, const float* __restrict__ bo,
                       const int* __restrict__ rp, const int* __restrict__ csrc,
                       float* __restrict__ gp, float* __restrict__ out) {
    constexpr int M   = H * C;
    constexpr int CAP = 256;
    constexpr int Q   = (M + TB - 1) / TB;
    __shared__ float s_xr[M], s_att[M];
    __shared__ float s_m[H], s_den[H], s_inv[H];
    __shared__ int   s_src[CAP];
    __shared__ float s_p[CAP * H];

    int dst = blockIdx.x;
    int tid = threadIdx.x;
    int start = rp[dst];
    int deg   = rp[dst + 1] - start;
    bool fits = (deg <= CAP);
    float* pb = fits ? s_p : (gp + (size_t)start * H);
    const int* srcp = fits ? s_src : (csrc + start);

    for (int j = tid; j < M; j += TB) {
        s_xr[j] = xr[(size_t)dst * M + j];
        s_att[j] = att[j];
    }
    if (tid < H) { s_m[tid] = -INFINITY; s_den[tid] = 0.f; }
    if (fits) for (int i = tid; i < deg; i += TB) s_src[i] = csrc[start + i];
    __syncthreads();

    // phase 1: logits (warp per edge), block max per head via shared CAS
    int wid = tid >> 5, lane = tid & 31;
    for (int e = wid; e < deg; e += TB / 32) {
        const float* xls = xl + (size_t)srcp[e] * M;
        #pragma unroll
        for (int h = 0; h < H; h++) {
            float s = 0.f;
            #pragma unroll
            for (int c = lane; c < C; c += 32) {
                int j = h * C + c;
                float v = xls[j] + s_xr[j];
                v = (v > 0.f) ? v : 0.2f * v;
                s = fmaf(s_att[j], v, s);
            }
            #pragma unroll
            for (int o = 16; o; o >>= 1) s += __shfl_xor_sync(0xffffffffu, s, o);
            if (lane == 0) {
                pb[e * H + h] = s;
                int* a = (int*)&s_m[h];
                int old = *a;
                while (__int_as_float(old) < s) {
                    int assumed = old;
                    old = atomicCAS(a, assumed, __float_as_int(s));
                    if (old == assumed) break;
                }
            }
        }
    }
    __syncthreads();

    // phase 2: exp + denominator
    for (int i = tid; i < deg * H; i += TB) {
        int h = i % H;
        float v = expf(pb[i] - s_m[h]);
        pb[i] = v;
        atomicAdd(&s_den[h], v);
    }
    __syncthreads();
    if (tid < H) s_inv[tid] = 1.0f / s_den[tid];
    __syncthreads();
    // scale probs -> alpha in place
    for (int i = tid; i < deg * H; i += TB) pb[i] *= s_inv[i % H];
    __syncthreads();

    // phase 3: alpha-weighted gather-aggregate
    float acc[Q];
    int hq[Q];
    #pragma unroll
    for (int q = 0; q < Q; q++) { acc[q] = 0.f; hq[q] = (tid + q * TB) / C; }
    #pragma unroll 2
    for (int e = 0; e < deg; e++) {
        const float* xls = xl + (size_t)srcp[e] * M;
        #pragma unroll
        for (int q = 0; q < Q; q++) {
            int j = tid + q * TB;
            if (j < M) acc[q] = fmaf(pb[e * H + hq[q]], xls[j], acc[q]);
        }
    }
    #pragma unroll
    for (int q = 0; q < Q; q++) {
        int j = tid + q * TB;
        if (j < M) out[(size_t)dst * M + j] = acc[q] + bo[j];
    }
}

// ---------------- pooling (sorted batch -> run-length local sums) ---------------
__global__ void k_pool2(const float* __restrict__ x, const int* __restrict__ batch,
                        float* __restrict__ gs, float* __restrict__ cnt) {
    int j = threadIdx.x;              // 0..63 feature
    int w = threadIdx.y;              // 0..3
    int i0 = blockIdx.x * 128;
    int iend = min(i0 + 128, N_NODES);
    float acc = 0.f, cn = 0.f;
    int curb = -1;
    for (int i = i0 + w; i < iend; i += 4) {
        int b = batch[i];
        if (b != curb) {
            if (curb >= 0) {
                atomicAdd(&gs[curb * 64 + j], acc);
                if (j == 0) atomicAdd(&cnt[curb], cn);
            }
            curb = b; acc = 0.f; cn = 0.f;
        }
        acc += x[(size_t)i * 64 + j];
        cn += 1.f;
    }
    if (curb >= 0) {
        atomicAdd(&gs[curb * 64 + j], acc);
        if (j == 0) atomicAdd(&cnt[curb], cn);
    }
}

__global__ void k_mlp(const float* __restrict__ gs, const float* __restrict__ cnt,
                      const float* __restrict__ demo,
                      const float* __restrict__ Wc1, const float* __restrict__ bc1,
                      const float* __restrict__ Wc2, const float* __restrict__ bc2,
                      float* __restrict__ out) {
    int g = blockIdx.x * blockDim.x + threadIdx.x;
    if (g >= G_GRAPHS) return;
    float inv = 1.0f / fmaxf(cnt[g], 1.0f);
    float in[69];
    #pragma unroll
    for (int j = 0; j < 64; j++) in[j] = gs[g * 64 + j] * inv;
    #pragma unroll
    for (int j = 0; j < 5; j++) in[64 + j] = demo[g * 5 + j];
    float h[32];
    #pragma unroll
    for (int o = 0; o < 32; o++) {
        float a = bc1[o];
        for (int i = 0; i < 69; i++) a = fmaf(in[i], Wc1[i * 32 + o], a);
        h[o] = fmaxf(a, 0.0f);
    }
    #pragma unroll
    for (int o = 0; o < 2; o++) {
        float a = bc2[o];
        #pragma unroll
        for (int i = 0; i < 32; i++) a = fmaf(h[i], Wc2[i * 2 + o], a);
        out[g * 2 + o] = a;
    }
}

// ---------------- launch --------------------------------------------------------
static inline int ceil_div(int a, int b) { return (a + b - 1) / b; }

extern "C" void kernel_launch(void* const* d_in, const int* in_sizes, int n_in,
                              void* d_out, int out_size) {
    const float* emb  = (const float*)d_in[0];
    const float* Wl0  = (const float*)d_in[1];
    const float* bl0  = (const float*)d_in[2];
    const float* Wr0  = (const float*)d_in[3];
    const float* br0  = (const float*)d_in[4];
    const float* att0 = (const float*)d_in[5];
    const float* bo0  = (const float*)d_in[6];
    const float* Wl1  = (const float*)d_in[7];
    const float* bl1  = (const float*)d_in[8];
    const float* Wr1  = (const float*)d_in[9];
    const float* br1  = (const float*)d_in[10];
    const float* att1 = (const float*)d_in[11];
    const float* bo1  = (const float*)d_in[12];
    const float* Wl2  = (const float*)d_in[13];
    const float* bl2  = (const float*)d_in[14];
    const float* Wr2  = (const float*)d_in[15];
    const float* br2  = (const float*)d_in[16];
    const float* att2 = (const float*)d_in[17];
    const float* bo2  = (const float*)d_in[18];
    const float* Wc1  = (const float*)d_in[19];
    const float* bc1  = (const float*)d_in[20];
    const float* Wc2  = (const float*)d_in[21];
    const float* bc2  = (const float*)d_in[22];
    const float* demo = (const float*)d_in[23];
    const int*   ids  = (const int*)d_in[24];
    const int*   ei   = (const int*)d_in[25];
    const int*   batch= (const int*)d_in[26];
    float* out = (float*)d_out;

    float *px, *pxl, *pxr, *pp, *pgs, *pcnt;
    int *pdeg, *prp, *pcur, *pcsrc, *ppart;
    cudaGetSymbolAddress((void**)&px,    g_x);
    cudaGetSymbolAddress((void**)&pxl,   g_xl);
    cudaGetSymbolAddress((void**)&pxr,   g_xr);
    cudaGetSymbolAddress((void**)&pp,    g_p);
    cudaGetSymbolAddress((void**)&pdeg,  g_deg);
    cudaGetSymbolAddress((void**)&prp,   g_rp);
    cudaGetSymbolAddress((void**)&pcur,  g_cur);
    cudaGetSymbolAddress((void**)&pcsrc, g_csrc);
    cudaGetSymbolAddress((void**)&ppart, g_part);
    cudaGetSymbolAddress((void**)&pgs,   g_gs);
    cudaGetSymbolAddress((void**)&pcnt,  g_cnt);

    const int T = 256;

    // embedding gather
    k_gather<<<ceil_div(N_NODES * 16, T), T>>>(emb, ids, px);

    // CSR by destination (shared by all three layers)
    k_fill_i<<<ceil_div(N_NODES, T), T>>>(pdeg, 0, N_NODES);
    k_count<<<ceil_div(E_TOT, T), T>>>(ei, pdeg);
    k_scan1<<<SCAN_NB, SCAN_B>>>(pdeg, ppart);
    k_scan2<<<1, 1>>>(ppart);
    k_scan3<<<SCAN_NB, SCAN_B>>>(pdeg, ppart, prp, pcur);
    k_scatter<<<ceil_div(E_TOT, T), T>>>(ei, pcur, pcsrc);

    // layer 0: 16 -> 3 heads x 32
    k_gemm2<16, 96, 32><<<ceil_div(N_NODES, 32), 96>>>(px, Wl0, bl0, Wr0, br0, pxl, pxr);
    k_attn<3, 32><<<N_NODES, TB>>>(pxl, pxr, att0, bo0, prp, pcsrc, pp, px);

    // layer 1: 96 -> 2 heads x 96
    k_gemm2<96, 192, 32><<<ceil_div(N_NODES, 32), 192>>>(px, Wl1, bl1, Wr1, br1, pxl, pxr);
    k_attn<2, 96><<<N_NODES, TB>>>(pxl, pxr, att1, bo1, prp, pcsrc, pp, px);

    // layer 2: 192 -> 1 head x 64
    k_gemm2<192, 64, 32><<<ceil_div(N_NODES, 32), 64>>>(px, Wl2, bl2, Wr2, br2, pxl, pxr);
    k_attn<1, 64><<<N_NODES, TB>>>(pxl, pxr, att2, bo2, prp, pcsrc, pp, px);

    // global mean pool + MLP head
    k_fill_f<<<ceil_div(G_GRAPHS * 64, T), T>>>(pgs, 0.0f, G_GRAPHS * 64);
    k_fill_f<<<1, G_GRAPHS>>>(pcnt, 0.0f, G_GRAPHS);
    dim3 pb(64, 4);
    k_pool2<<<ceil_div(N_NODES, 128), pb>>>(px, batch, pgs, pcnt);
    k_mlp<<<1, G_GRAPHS>>>(pgs, pcnt, demo, Wc1, bc1, Wc2, bc2, out);
}